// round 6
// baseline (speedup 1.0000x reference)
#include <cuda_runtime.h>
#include <cstdint>

// Problem constants
#define N_T 9
#define N_Y 32
#define N_X 32
#define NB  1024              // N_X * N_Y
#define TN  (N_T * NB)        // 9216

// Stencil coefficients of invM = I + A for timesteps k = 0..7 (params at t=k+1).
// Layout: d_B[k][node][d], d = (dy+1)*3 + (dx+1). Entries for out-of-bounds
// neighbors are stored as 0 (Dirichlet BC drops them).
__device__ float d_B[8 * NB * 9];

__global__ void coef_kernel(const float* __restrict__ kappa,
                            const float* __restrict__ m,
                            const float* __restrict__ H) {
    int idx = blockIdx.x * blockDim.x + threadIdx.x;
    if (idx >= 8 * NB) return;
    int k = idx >> 10;          // timestep block 0..7
    int p = idx & (NB - 1);     // node
    int t = k + 1;              // parameter time index
    int iy = p >> 5, ix = p & 31;

    float kap = kappa[p * N_T + t];
    float k2  = kap * kap;
    float m1  = m[(0 * NB + p) * N_T + t];
    float m2  = m[(1 * NB + p) * N_T + t];
    float H11 = H[(0 * NB + p) * N_T + t];
    float H12 = H[(1 * NB + p) * N_T + t];
    float H22 = H[(3 * NB + p) * N_T + t];

    float c[9];
    c[4] = 1.0f + k2 + 2.0f * H11 + 2.0f * H22;  // center (invM: +1)
    c[5] =  0.5f * m1 - H11;   // (dy=0, dx=+1)
    c[3] = -0.5f * m1 - H11;   // (dy=0, dx=-1)
    c[7] =  0.5f * m2 - H22;   // (dy=+1, dx=0)
    c[1] = -0.5f * m2 - H22;   // (dy=-1, dx=0)
    c[8] = -0.5f * H12;        // (+1,+1)
    c[0] = -0.5f * H12;        // (-1,-1)
    c[2] =  0.5f * H12;        // (-1,+1)
    c[6] =  0.5f * H12;        // (+1,-1)

#pragma unroll
    for (int d = 0; d < 9; d++) {
        int dy = d / 3 - 1, dx = d % 3 - 1;
        int jy = iy + dy, jx = ix + dx;
        bool ok = (jy >= 0 && jy < N_Y && jx >= 0 && jx < N_X);
        d_B[(k * NB + p) * 9 + d] = ok ? c[d] : 0.0f;
    }
}

// Zero the whole 340 MB output with wide stores — this is the roofline cost.
// One float4 per thread, no loop: TN*TN/4 = 21,233,664 threads.
__global__ void zero_kernel(float4* __restrict__ out) {
    size_t i = (size_t)blockIdx.x * blockDim.x + threadIdx.x;
    out[i] = make_float4(0.f, 0.f, 0.f, 0.f);
}

// Diagonal blocks: t=0 -> A0^T A0 + 1.05 I ; t=1..7 -> sym(MM[t-1]) + 1.05 I ;
// t=8 -> sym(MM[7]) + 0.05 I. All within a 5x5 stencil neighborhood per row.
__global__ void diag_kernel(float* __restrict__ out) {
    int idx = blockIdx.x * blockDim.x + threadIdx.x;
    if (idx >= N_T * NB) return;
    int t = idx >> 10;
    int p = idx & (NB - 1);
    int iy = p >> 5, ix = p & 31;
    float* row = out + (size_t)(t * NB + p) * TN + (size_t)t * NB;

    if (t == 0) {
        const float* B0 = d_B;  // k = 0
        for (int dqy = -2; dqy <= 2; dqy++) {
            for (int dqx = -2; dqx <= 2; dqx++) {
                int qy = iy + dqy, qx = ix + dqx;
                if (qy < 0 || qy >= N_Y || qx < 0 || qx >= N_X) continue;
                int q = qy * N_X + qx;
                float s = 0.0f;
                // (A^T A)[p,q] = sum_r A[r, p-r] * A[r, q-r], r in both stencils
#pragma unroll
                for (int e1 = 0; e1 < 9; e1++) {
                    int e1y = e1 / 3 - 1, e1x = e1 % 3 - 1;
                    int ry = iy - e1y, rx = ix - e1x;
                    if (ry < 0 || ry >= N_Y || rx < 0 || rx >= N_X) continue;
                    int e2y = dqy + e1y, e2x = dqx + e1x;
                    if (e2y < -1 || e2y > 1 || e2x < -1 || e2x > 1) continue;
                    int r = ry * N_X + rx;
                    int e2 = (e2y + 1) * 3 + (e2x + 1);
                    float a1 = B0[r * 9 + e1] - (e1 == 4 ? 1.0f : 0.0f);
                    float a2 = B0[r * 9 + e2] - (e2 == 4 ? 1.0f : 0.0f);
                    s += a1 * a2;
                }
                if (q == p) s += 1.05f;
                row[q] = s;
            }
        }
    } else {
        int k = t - 1;
        const float* Bk = d_B + k * NB * 9;
        float diag_add = (t < N_T - 1) ? 1.05f : 0.05f;
        for (int dqy = -2; dqy <= 2; dqy++) {
            for (int dqx = -2; dqx <= 2; dqx++) {
                int qy = iy + dqy, qx = ix + dqx;
                if (qy < 0 || qy >= N_Y || qx < 0 || qx >= N_X) continue;
                int q = qy * N_X + qx;
                // MM[p,q] = sum_{d1} B[p,d1] * B[p+d1, dq-d1]
                float s1 = 0.0f;
#pragma unroll
                for (int d1 = 0; d1 < 9; d1++) {
                    int d1y = d1 / 3 - 1, d1x = d1 % 3 - 1;
                    int ry = iy + d1y, rx = ix + d1x;
                    if (ry < 0 || ry >= N_Y || rx < 0 || rx >= N_X) continue;
                    int d2y = dqy - d1y, d2x = dqx - d1x;
                    if (d2y < -1 || d2y > 1 || d2x < -1 || d2x > 1) continue;
                    int r = ry * N_X + rx;
                    int d2 = (d2y + 1) * 3 + (d2x + 1);
                    s1 += Bk[p * 9 + d1] * Bk[r * 9 + d2];
                }
                // MM[q,p] = sum_{d1} B[q,d1] * B[q+d1, -dq-d1]
                float s2 = 0.0f;
#pragma unroll
                for (int d1 = 0; d1 < 9; d1++) {
                    int d1y = d1 / 3 - 1, d1x = d1 % 3 - 1;
                    int ry = qy + d1y, rx = qx + d1x;
                    if (ry < 0 || ry >= N_Y || rx < 0 || rx >= N_X) continue;
                    int d2y = -dqy - d1y, d2x = -dqx - d1x;
                    if (d2y < -1 || d2y > 1 || d2x < -1 || d2x > 1) continue;
                    int r = ry * N_X + rx;
                    int d2 = (d2y + 1) * 3 + (d2x + 1);
                    s2 += Bk[q * 9 + d1] * Bk[r * 9 + d2];
                }
                float v = 0.5f * (s1 + s2);
                if (q == p) v += diag_add;
                row[q] = v;
            }
        }
    }
}

// Off-diagonal blocks (k,k+1) and (k+1,k), both equal to -0.5*(B_k + B_k^T).
__global__ void offdiag_kernel(float* __restrict__ out) {
    int idx = blockIdx.x * blockDim.x + threadIdx.x;
    if (idx >= 8 * NB) return;
    int k = idx >> 10;
    int p = idx & (NB - 1);
    int iy = p >> 5, ix = p & 31;
    const float* Bk = d_B + k * NB * 9;
    size_t rowU = (size_t)(k * NB + p) * TN + (size_t)(k + 1) * NB;
    size_t rowL = (size_t)((k + 1) * NB + p) * TN + (size_t)k * NB;
#pragma unroll
    for (int d = 0; d < 9; d++) {
        int dy = d / 3 - 1, dx = d % 3 - 1;
        int qy = iy + dy, qx = ix + dx;
        if (qy < 0 || qy >= N_Y || qx < 0 || qx >= N_X) continue;
        int q = qy * N_X + qx;
        float v = -0.5f * (Bk[p * 9 + d] + Bk[q * 9 + (8 - d)]);
        out[rowU + q] = v;
        out[rowL + q] = v;
    }
}

extern "C" void kernel_launch(void* const* d_in, const int* in_sizes, int n_in,
                              void* d_out, int out_size) {
    const float* kappa = (const float*)d_in[0];
    const float* m     = (const float*)d_in[1];
    const float* H     = (const float*)d_in[2];
    // d_in[3] = tau, unused (reference discards it)
    float* out = (float*)d_out;

    // 1) stencil coefficients for invM (8 timesteps x 1024 nodes x 9 dirs)
    coef_kernel<<<(8 * NB + 255) / 256, 256>>>(kappa, m, H);

    // 2) zero the entire output (dominant cost: 340 MB of stores)
    // TN*TN/4 float4s = 21,233,664; 256 threads/block -> 82,944 blocks exactly.
    zero_kernel<<<(unsigned)(((size_t)TN * TN / 4) / 256), 256>>>((float4*)out);

    // 3) scatter nonzero entries (stream-ordered after the zero fill)
    diag_kernel<<<(N_T * NB + 255) / 256, 256>>>(out);
    offdiag_kernel<<<(8 * NB + 255) / 256, 256>>>(out);
}

// round 12
// speedup vs baseline: 1.1940x; 1.1940x over previous
#include <cuda_runtime.h>
#include <cstdint>

// Problem constants
#define N_T 9
#define N_Y 32
#define N_X 32
#define NB  1024              // N_X * N_Y
#define TN  (N_T * NB)        // 9216

// Stencil coefficients of invM = I + A for timesteps k = 0..7 (params at t=k+1).
// Layout: d_B[k][node][d], d = (dy+1)*3 + (dx+1). OOB-neighbor entries = 0.
__device__ float d_B[8 * NB * 9];
// Precomputed diagonal-block values: [t*NB+p][ (dqy+2)*5 + (dqx+2) ]  (5x5 window)
__device__ float d_diag[N_T * NB * 25];
// Precomputed off-diagonal values (same for upper & lower by symmetry):
// [k*NB+p][ (dqy+1)*3 + (dqx+1) ]
__device__ float d_off[8 * NB * 9];

__global__ void coef_kernel(const float* __restrict__ kappa,
                            const float* __restrict__ m,
                            const float* __restrict__ H) {
    int idx = blockIdx.x * blockDim.x + threadIdx.x;
    if (idx >= 8 * NB) return;
    int k = idx >> 10;          // timestep block 0..7
    int p = idx & (NB - 1);     // node
    int t = k + 1;              // parameter time index
    int iy = p >> 5, ix = p & 31;

    float kap = kappa[p * N_T + t];
    float k2  = kap * kap;
    float m1  = m[(0 * NB + p) * N_T + t];
    float m2  = m[(1 * NB + p) * N_T + t];
    float H11 = H[(0 * NB + p) * N_T + t];
    float H12 = H[(1 * NB + p) * N_T + t];
    float H22 = H[(3 * NB + p) * N_T + t];

    float c[9];
    c[4] = 1.0f + k2 + 2.0f * H11 + 2.0f * H22;  // center (invM: +1)
    c[5] =  0.5f * m1 - H11;   // (dy=0, dx=+1)
    c[3] = -0.5f * m1 - H11;   // (dy=0, dx=-1)
    c[7] =  0.5f * m2 - H22;   // (dy=+1, dx=0)
    c[1] = -0.5f * m2 - H22;   // (dy=-1, dx=0)
    c[8] = -0.5f * H12;        // (+1,+1)
    c[0] = -0.5f * H12;        // (-1,-1)
    c[2] =  0.5f * H12;        // (-1,+1)
    c[6] =  0.5f * H12;        // (+1,-1)

#pragma unroll
    for (int d = 0; d < 9; d++) {
        int dy = d / 3 - 1, dx = d % 3 - 1;
        int jy = iy + dy, jx = ix + dx;
        bool ok = (jy >= 0 && jy < N_Y && jx >= 0 && jx < N_X);
        d_B[(k * NB + p) * 9 + d] = ok ? c[d] : 0.0f;
    }
}

// One thread per nonzero entry: first N_T*NB*25 threads compute diagonal-block
// entries, the next 8*NB*9 compute off-diagonal entries.
#define N_DIAG_ENT (N_T * NB * 25)
#define N_OFF_ENT  (8 * NB * 9)
__global__ void prep_kernel() {
    int idx = blockIdx.x * blockDim.x + threadIdx.x;
    if (idx < N_DIAG_ENT) {
        int e   = idx % 25;
        int row = idx / 25;          // t*NB + p
        int t = row >> 10;
        int p = row & (NB - 1);
        int iy = p >> 5, ix = p & 31;
        int dqy = e / 5 - 2, dqx = e % 5 - 2;
        int qy = iy + dqy, qx = ix + dqx;
        if (qy < 0 || qy >= N_Y || qx < 0 || qx >= N_X) return;  // slot never read
        int q = qy * N_X + qx;
        float v;
        if (t == 0) {
            const float* B0 = d_B;
            float s = 0.0f;
#pragma unroll
            for (int e1 = 0; e1 < 9; e1++) {
                int e1y = e1 / 3 - 1, e1x = e1 % 3 - 1;
                int ry = iy - e1y, rx = ix - e1x;
                if (ry < 0 || ry >= N_Y || rx < 0 || rx >= N_X) continue;
                int e2y = dqy + e1y, e2x = dqx + e1x;
                if (e2y < -1 || e2y > 1 || e2x < -1 || e2x > 1) continue;
                int r = ry * N_X + rx;
                int e2 = (e2y + 1) * 3 + (e2x + 1);
                float a1 = B0[r * 9 + e1] - (e1 == 4 ? 1.0f : 0.0f);
                float a2 = B0[r * 9 + e2] - (e2 == 4 ? 1.0f : 0.0f);
                s += a1 * a2;
            }
            v = s + (q == p ? 1.05f : 0.0f);
        } else {
            int k = t - 1;
            const float* Bk = d_B + k * NB * 9;
            float diag_add = (t < N_T - 1) ? 1.05f : 0.05f;
            float s1 = 0.0f;
#pragma unroll
            for (int d1 = 0; d1 < 9; d1++) {
                int d1y = d1 / 3 - 1, d1x = d1 % 3 - 1;
                int ry = iy + d1y, rx = ix + d1x;
                if (ry < 0 || ry >= N_Y || rx < 0 || rx >= N_X) continue;
                int d2y = dqy - d1y, d2x = dqx - d1x;
                if (d2y < -1 || d2y > 1 || d2x < -1 || d2x > 1) continue;
                int r = ry * N_X + rx;
                int d2 = (d2y + 1) * 3 + (d2x + 1);
                s1 += Bk[p * 9 + d1] * Bk[r * 9 + d2];
            }
            float s2 = 0.0f;
#pragma unroll
            for (int d1 = 0; d1 < 9; d1++) {
                int d1y = d1 / 3 - 1, d1x = d1 % 3 - 1;
                int ry = qy + d1y, rx = qx + d1x;
                if (ry < 0 || ry >= N_Y || rx < 0 || rx >= N_X) continue;
                int d2y = -dqy - d1y, d2x = -dqx - d1x;
                if (d2y < -1 || d2y > 1 || d2x < -1 || d2x > 1) continue;
                int r = ry * N_X + rx;
                int d2 = (d2y + 1) * 3 + (d2x + 1);
                s2 += Bk[q * 9 + d1] * Bk[r * 9 + d2];
            }
            v = 0.5f * (s1 + s2) + (q == p ? diag_add : 0.0f);
        }
        d_diag[(size_t)row * 25 + e] = v;
    } else if (idx < N_DIAG_ENT + N_OFF_ENT) {
        int idx2 = idx - N_DIAG_ENT;
        int d = idx2 % 9;
        int kp = idx2 / 9;            // k*NB + p
        int k = kp >> 10;
        int p = kp & (NB - 1);
        int iy = p >> 5, ix = p & 31;
        int dy = d / 3 - 1, dx = d % 3 - 1;
        int qy = iy + dy, qx = ix + dx;
        if (qy < 0 || qy >= N_Y || qx < 0 || qx >= N_X) return;  // slot never read
        int q = qy * N_X + qx;
        const float* Bk = d_B + k * NB * 9;
        d_off[(size_t)kp * 9 + d] = -0.5f * (Bk[p * 9 + d] + Bk[q * 9 + (8 - d)]);
    }
}

// Fused single-pass fill: writes every float4 of the 340 MB output exactly once.
// Zero outside the block-tridiagonal band; inside, look up precomputed values.
__global__ void fill_kernel(float4* __restrict__ out) {
    size_t i = (size_t)blockIdx.x * blockDim.x + threadIdx.x;   // < 21,233,664
    unsigned ii = (unsigned)i;
    unsigned r  = ii / (TN / 4);                 // output row, 0..9215
    unsigned c4 = ii - r * (TN / 4);
    unsigned col = c4 * 4;                       // first of 4 columns
    unsigned t = r >> 10, p = r & (NB - 1);
    unsigned u = col >> 10, q0 = col & (NB - 1);

    float4 v = make_float4(0.f, 0.f, 0.f, 0.f);
    int dt = (int)u - (int)t;
    if (dt * dt <= 1) {
        int iy = (int)(p >> 5), ix = (int)(p & 31);
        int qy = (int)(q0 >> 5), qxb = (int)(q0 & 31);   // q0..q0+3 share qy
        int dqy = qy - iy;
        float* vf = (float*)&v;
        if (dt == 0) {
            if (dqy >= -2 && dqy <= 2) {
                const float* dv = d_diag + (size_t)r * 25 + (dqy + 2) * 5;
#pragma unroll
                for (int j = 0; j < 4; j++) {
                    int dqx = qxb + j - ix;
                    if (dqx >= -2 && dqx <= 2) vf[j] = dv[dqx + 2];
                }
            }
        } else {
            if (dqy >= -1 && dqy <= 1) {
                int k = (dt > 0) ? (int)t : (int)u;       // min(t,u)
                const float* ov = d_off + ((size_t)(k << 10) + p) * 9 + (dqy + 1) * 3;
#pragma unroll
                for (int j = 0; j < 4; j++) {
                    int dqx = qxb + j - ix;
                    if (dqx >= -1 && dqx <= 1) vf[j] = ov[dqx + 1];
                }
            }
        }
    }
    out[i] = v;
}

extern "C" void kernel_launch(void* const* d_in, const int* in_sizes, int n_in,
                              void* d_out, int out_size) {
    const float* kappa = (const float*)d_in[0];
    const float* m     = (const float*)d_in[1];
    const float* H     = (const float*)d_in[2];
    // d_in[3] = tau, unused (reference discards it)
    float* out = (float*)d_out;

    // 1) stencil coefficients for invM (8 timesteps x 1024 nodes x 9 dirs)
    coef_kernel<<<(8 * NB + 255) / 256, 256>>>(kappa, m, H);

    // 2) one thread per nonzero entry -> compact value tables (L2-resident)
    prep_kernel<<<(N_DIAG_ENT + N_OFF_ENT + 255) / 256, 256>>>();

    // 3) single fused pass over the whole 340 MB output.
    // TN*TN/4 float4s = 21,233,664; 256 threads/block -> 82,944 blocks exactly.
    fill_kernel<<<(unsigned)(((size_t)TN * TN / 4) / 256), 256>>>((float4*)out);
}